// round 1
// baseline (speedup 1.0000x reference)
#include <cuda_runtime.h>
#include <math.h>

#define BB 8
#define CC 256
#define TT 16
#define HWN 1024
#define CR 16
#define TILE 32

// ---------------- scratch (device globals; no allocation allowed) ----------
__device__ float g_sp[BB * CC * HWN];   // spatial pooled mean  [b, c, hw]
__device__ float g_tp[BB * CC * TT];    // temporal pooled mean [b, c, t]
__device__ float g_cp[BB * CC];         // channel pooled mean  [b, c]
__device__ float g_comb[BB * CC * TT];  // temporal_att * channel_att

__device__ __forceinline__ float sigmoidf(float a) {
    return 1.0f / (1.0f + __expf(-a));
}

// ---------------- K1: pooling -----------------------------------------------
// one block per (b,c); 256 threads; float4 loads; sp in registers,
// per-t partials warp/smem reduced.
__global__ void pool_kernel(const float* __restrict__ x) {
    const int bc  = blockIdx.x;
    const int tid = threadIdx.x;
    const float4* xb = (const float4*)(x + (size_t)bc * (TT * HWN));

    float4 sp = make_float4(0.f, 0.f, 0.f, 0.f);
    float tpar[TT];

#pragma unroll
    for (int t = 0; t < TT; t++) {
        float4 v = xb[t * (HWN / 4) + tid];
        sp.x += v.x; sp.y += v.y; sp.z += v.z; sp.w += v.w;
        tpar[t] = (v.x + v.y) + (v.z + v.w);
    }

    // spatial mean (mean over T=16)
    float4 spo;
    spo.x = sp.x * (1.f / TT); spo.y = sp.y * (1.f / TT);
    spo.z = sp.z * (1.f / TT); spo.w = sp.w * (1.f / TT);
    ((float4*)(g_sp + (size_t)bc * HWN))[tid] = spo;

    // temporal partials: warp reduce, then cross-warp in smem
    __shared__ float wsum[8][TT];
    const int lane = tid & 31;
    const int wid  = tid >> 5;
#pragma unroll
    for (int t = 0; t < TT; t++) {
        float s = tpar[t];
#pragma unroll
        for (int off = 16; off > 0; off >>= 1)
            s += __shfl_down_sync(0xffffffffu, s, off);
        if (lane == 0) wsum[wid][t] = s;
    }
    __syncthreads();
    if (tid < TT) {
        float s = 0.f;
#pragma unroll
        for (int w = 0; w < 8; w++) s += wsum[w][tid];
        g_tp[bc * TT + tid] = s * (1.f / HWN);
        wsum[0][tid] = s;  // column-distinct; no race
    }
    __syncthreads();
    if (tid == 0) {
        float tot = 0.f;
#pragma unroll
        for (int t = 0; t < TT; t++) tot += wsum[0][t];
        g_cp[bc] = tot * (1.f / (TT * HWN));
    }
}

// ---------------- K2: temporal + channel SE -> comb --------------------------
// one block per (b,t); 256 threads (== C)
__global__ void small_se_kernel(const float* __restrict__ wt1, const float* __restrict__ bt1,
                                const float* __restrict__ wt2, const float* __restrict__ bt2,
                                const float* __restrict__ wc1, const float* __restrict__ bc1,
                                const float* __restrict__ wc2, const float* __restrict__ bc2) {
    const int b   = blockIdx.x >> 4;
    const int t   = blockIdx.x & 15;
    const int tid = threadIdx.x;

    __shared__ float pt[CC], pc[CC], hids[2 * CR];

    pt[tid] = g_tp[(b * CC + tid) * TT + t];
    pc[tid] = g_cp[b * CC + tid];
    __syncthreads();

    if (tid < CR) {
        float s = bt1[tid];
        for (int c = 0; c < CC; c++) s = fmaf(wt1[tid * CC + c], pt[c], s);
        hids[tid] = fmaxf(s, 0.f);
    } else if (tid < 2 * CR) {
        const int r = tid - CR;
        float s = bc1[r];
        for (int c = 0; c < CC; c++) s = fmaf(wc1[r * CC + c], pc[c], s);
        hids[tid] = fmaxf(s, 0.f);
    }
    __syncthreads();

    float at = bt2[tid];
    float ac = bc2[tid];
#pragma unroll
    for (int r = 0; r < CR; r++) {
        at = fmaf(wt2[tid * CR + r], hids[r],      at);
        ac = fmaf(wc2[tid * CR + r], hids[CR + r], ac);
    }
    g_comb[(b * CC + tid) * TT + t] = sigmoidf(at) * sigmoidf(ac);
}

// ---------------- K3: fused spatial SE + apply -------------------------------
// one block per (b, 32-hw tile); 256 threads.
// smem layout (floats): w1s[4096] w2s[4096] combs[4096] stage[4096]
//                       atts[8192] b2s[256] b1s[16]  -> 24848 f = 99392 B
#define K3_SMEM_FLOATS (4096 * 4 + 8192 + 256 + 16)

__global__ void se_apply_kernel(const float* __restrict__ x,
                                const float* __restrict__ ws1, const float* __restrict__ bs1,
                                const float* __restrict__ ws2, const float* __restrict__ bs2,
                                float* __restrict__ out) {
    extern __shared__ float sm[];
    float* w1s   = sm;                 // [CR][C]    4096
    float* w2s   = w1s + CR * CC;      // [C][CR]    4096
    float* combs = w2s + CC * CR;      // [C][T]     4096
    float* stage = combs + CC * TT;    // [8][CR][TILE] 4096
    float* atts  = stage + 8 * CR * TILE; // [C][TILE]  8192
    float* b2s   = atts + CC * TILE;   // 256
    float* b1s   = b2s + CC;           // 16

    const int bx  = blockIdx.x;
    const int b   = bx >> 5;
    const int hw0 = (bx & 31) * TILE;
    const int tid = threadIdx.x;

    for (int i = tid; i < CR * CC; i += 256) { w1s[i] = ws1[i]; w2s[i] = ws2[i]; }
    for (int i = tid; i < CC * TT; i += 256) combs[i] = g_comb[b * (CC * TT) + i];
    if (tid < CC) b2s[tid] = bs2[tid];
    if (tid < CR) b1s[tid] = bs1[tid];
    __syncthreads();

    // ---- spatial SE for this tile: 8-way channel split ----
    const int hw_l = tid & (TILE - 1);  // 0..31
    const int g    = tid >> 5;          // 0..7  -> channels g*32..g*32+31

    float hid[CR];
#pragma unroll
    for (int r = 0; r < CR; r++) hid[r] = 0.f;

    const float* spb = g_sp + (size_t)(b * CC) * HWN + hw0 + hw_l;
#pragma unroll 4
    for (int ccv = 0; ccv < 32; ccv++) {
        const int c = g * 32 + ccv;
        const float v = spb[(size_t)c * HWN];
#pragma unroll
        for (int r = 0; r < CR; r++) hid[r] = fmaf(w1s[r * CC + c], v, hid[r]);
    }
#pragma unroll
    for (int r = 0; r < CR; r++) stage[(g * CR + r) * TILE + hw_l] = hid[r];
    __syncthreads();

    float hf[CR];
#pragma unroll
    for (int r = 0; r < CR; r++) {
        float s = b1s[r];
#pragma unroll
        for (int gg = 0; gg < 8; gg++) s += stage[(gg * CR + r) * TILE + hw_l];
        hf[r] = fmaxf(s, 0.f);
    }

#pragma unroll 4
    for (int ccv = 0; ccv < 32; ccv++) {
        const int c = g * 32 + ccv;
        float a = b2s[c];
#pragma unroll
        for (int r = 0; r < CR; r++) a = fmaf(w2s[c * CR + r], hf[r], a);
        atts[c * TILE + hw_l] = sigmoidf(a);
    }
    __syncthreads();

    // ---- apply: out = x * spatial_att * comb ----
    const size_t xb = (size_t)b * (CC * TT * HWN);
    const float4* xp = (const float4*)(x + xb);
    float4* op       = (float4*)(out + xb);
    const int f4 = tid & 7;    // 8 float4 per 32-float hw segment
    const int pg = tid >> 3;   // 32 (c,t) pairs per iteration

#pragma unroll 4
    for (int i = 0; i < 128; i++) {
        const int pair = i * 32 + pg;      // 0..4095
        const int c = pair >> 4;
        const int t = pair & 15;
        const int idx = (c * TT + t) * (HWN / 4) + (hw0 >> 2) + f4;
        float4 v  = xp[idx];
        float4 a4 = *(const float4*)&atts[c * TILE + f4 * 4];
        const float s = combs[c * TT + t];
        v.x = v.x * a4.x * s;
        v.y = v.y * a4.y * s;
        v.z = v.z * a4.z * s;
        v.w = v.w * a4.w * s;
        op[idx] = v;
    }
}

// ---------------- launch -----------------------------------------------------
extern "C" void kernel_launch(void* const* d_in, const int* in_sizes, int n_in,
                              void* d_out, int out_size) {
    const float* x   = (const float*)d_in[0];
    const float* ws1 = (const float*)d_in[1];
    const float* bs1 = (const float*)d_in[2];
    const float* ws2 = (const float*)d_in[3];
    const float* bs2 = (const float*)d_in[4];
    const float* wt1 = (const float*)d_in[5];
    const float* bt1 = (const float*)d_in[6];
    const float* wt2 = (const float*)d_in[7];
    const float* bt2 = (const float*)d_in[8];
    const float* wc1 = (const float*)d_in[9];
    const float* bc1 = (const float*)d_in[10];
    const float* wc2 = (const float*)d_in[11];
    const float* bc2 = (const float*)d_in[12];
    float* out = (float*)d_out;

    pool_kernel<<<BB * CC, 256>>>(x);
    small_se_kernel<<<BB * TT, 256>>>(wt1, bt1, wt2, bt2, wc1, bc1, wc2, bc2);

    const int smem_bytes = K3_SMEM_FLOATS * (int)sizeof(float);
    cudaFuncSetAttribute(se_apply_kernel,
                         cudaFuncAttributeMaxDynamicSharedMemorySize, smem_bytes);
    se_apply_kernel<<<BB * 32, 256, smem_bytes>>>(x, ws1, bs1, ws2, bs2, out);
}

// round 2
// speedup vs baseline: 1.1537x; 1.1537x over previous
#include <cuda_runtime.h>
#include <math.h>

#define BB 8
#define CC 256
#define TT 16
#define HWN 1024
#define CR 16
#define TILE 32

// ---------------- scratch (device globals; no allocation allowed) ----------
__device__ float g_sp[BB * CC * HWN];   // spatial pooled mean  [b, c, hw]
__device__ float g_tp[BB * CC * TT];    // temporal pooled mean [b, c, t]
__device__ float g_cp[BB * CC];         // channel pooled mean  [b, c]
__device__ float g_comb[BB * CC * TT];  // temporal_att * channel_att
__device__ float g_att[BB * CC * HWN];  // spatial attention    [b, c, hw]

__device__ __forceinline__ float sigmoidf(float a) {
    return 1.0f / (1.0f + __expf(-a));
}

// ---------------- K1: pooling -----------------------------------------------
// one block per (b,c); 256 threads; float4 loads; sp in registers,
// per-t partials warp/smem reduced.
__global__ void pool_kernel(const float* __restrict__ x) {
    const int bc  = blockIdx.x;
    const int tid = threadIdx.x;
    const float4* xb = (const float4*)(x + (size_t)bc * (TT * HWN));

    float4 sp = make_float4(0.f, 0.f, 0.f, 0.f);
    float tpar[TT];

#pragma unroll
    for (int t = 0; t < TT; t++) {
        float4 v = xb[t * (HWN / 4) + tid];
        sp.x += v.x; sp.y += v.y; sp.z += v.z; sp.w += v.w;
        tpar[t] = (v.x + v.y) + (v.z + v.w);
    }

    // spatial mean (mean over T=16)
    float4 spo;
    spo.x = sp.x * (1.f / TT); spo.y = sp.y * (1.f / TT);
    spo.z = sp.z * (1.f / TT); spo.w = sp.w * (1.f / TT);
    ((float4*)(g_sp + (size_t)bc * HWN))[tid] = spo;

    // temporal partials: warp reduce, then cross-warp in smem
    __shared__ float wsum[8][TT];
    const int lane = tid & 31;
    const int wid  = tid >> 5;
#pragma unroll
    for (int t = 0; t < TT; t++) {
        float s = tpar[t];
#pragma unroll
        for (int off = 16; off > 0; off >>= 1)
            s += __shfl_down_sync(0xffffffffu, s, off);
        if (lane == 0) wsum[wid][t] = s;
    }
    __syncthreads();
    if (tid < TT) {
        float s = 0.f;
#pragma unroll
        for (int w = 0; w < 8; w++) s += wsum[w][tid];
        g_tp[bc * TT + tid] = s * (1.f / HWN);
        wsum[0][tid] = s;  // column-distinct; no race
    }
    __syncthreads();
    if (tid == 0) {
        float tot = 0.f;
#pragma unroll
        for (int t = 0; t < TT; t++) tot += wsum[0][t];
        g_cp[bc] = tot * (1.f / (TT * HWN));
    }
}

// ---------------- K2: temporal + channel SE -> comb --------------------------
// one block per (b,t); 256 threads (== C)
__global__ void small_se_kernel(const float* __restrict__ wt1, const float* __restrict__ bt1,
                                const float* __restrict__ wt2, const float* __restrict__ bt2,
                                const float* __restrict__ wc1, const float* __restrict__ bc1,
                                const float* __restrict__ wc2, const float* __restrict__ bc2) {
    const int b   = blockIdx.x >> 4;
    const int t   = blockIdx.x & 15;
    const int tid = threadIdx.x;

    __shared__ float pt[CC], pc[CC], hids[2 * CR];

    pt[tid] = g_tp[(b * CC + tid) * TT + t];
    pc[tid] = g_cp[b * CC + tid];
    __syncthreads();

    if (tid < CR) {
        float s = bt1[tid];
        for (int c = 0; c < CC; c++) s = fmaf(wt1[tid * CC + c], pt[c], s);
        hids[tid] = fmaxf(s, 0.f);
    } else if (tid < 2 * CR) {
        const int r = tid - CR;
        float s = bc1[r];
        for (int c = 0; c < CC; c++) s = fmaf(wc1[r * CC + c], pc[c], s);
        hids[tid] = fmaxf(s, 0.f);
    }
    __syncthreads();

    float at = bt2[tid];
    float ac = bc2[tid];
#pragma unroll
    for (int r = 0; r < CR; r++) {
        at = fmaf(wt2[tid * CR + r], hids[r],      at);
        ac = fmaf(wc2[tid * CR + r], hids[CR + r], ac);
    }
    g_comb[(b * CC + tid) * TT + t] = sigmoidf(at) * sigmoidf(ac);
}

// ---------------- K3a: spatial SE -> g_att -----------------------------------
// one block per (b, 32-hw tile); 256 threads.
// smem floats: w1s[4096] w2s[4096] stage[4096] b2s[256] b1s[16] = 12464 (~50KB)
#define K3A_SMEM_FLOATS (4096 * 3 + 256 + 16)

__global__ void spatial_se_kernel(const float* __restrict__ ws1, const float* __restrict__ bs1,
                                  const float* __restrict__ ws2, const float* __restrict__ bs2) {
    extern __shared__ float sm[];
    float* w1s   = sm;                    // [CR][C]       4096
    float* w2s   = w1s + CR * CC;         // [C][CR]       4096
    float* stage = w2s + CC * CR;         // [8][CR][TILE] 4096
    float* b2s   = stage + 8 * CR * TILE; // 256
    float* b1s   = b2s + CC;              // 16

    const int bx  = blockIdx.x;
    const int b   = bx >> 5;
    const int hw0 = (bx & 31) * TILE;
    const int tid = threadIdx.x;

    for (int i = tid; i < CR * CC; i += 256) { w1s[i] = ws1[i]; w2s[i] = ws2[i]; }
    if (tid < CC) b2s[tid] = bs2[tid];
    if (tid < CR) b1s[tid] = bs1[tid];
    __syncthreads();

    const int hw_l = tid & (TILE - 1);  // 0..31
    const int g    = tid >> 5;          // 0..7  -> channels g*32..g*32+31

    float hid[CR];
#pragma unroll
    for (int r = 0; r < CR; r++) hid[r] = 0.f;

    const float* spb = g_sp + (size_t)(b * CC) * HWN + hw0 + hw_l;
#pragma unroll 4
    for (int ccv = 0; ccv < 32; ccv++) {
        const int c = g * 32 + ccv;
        const float v = spb[(size_t)c * HWN];
#pragma unroll
        for (int r = 0; r < CR; r++) hid[r] = fmaf(w1s[r * CC + c], v, hid[r]);
    }
#pragma unroll
    for (int r = 0; r < CR; r++) stage[(g * CR + r) * TILE + hw_l] = hid[r];
    __syncthreads();

    float hf[CR];
#pragma unroll
    for (int r = 0; r < CR; r++) {
        float s = b1s[r];
#pragma unroll
        for (int gg = 0; gg < 8; gg++) s += stage[(gg * CR + r) * TILE + hw_l];
        hf[r] = fmaxf(s, 0.f);
    }

    float* attb = g_att + (size_t)(b * CC) * HWN + hw0 + hw_l;
#pragma unroll 4
    for (int ccv = 0; ccv < 32; ccv++) {
        const int c = g * 32 + ccv;
        float a = b2s[c];
#pragma unroll
        for (int r = 0; r < CR; r++) a = fmaf(w2s[c * CR + r], hf[r], a);
        attb[(size_t)c * HWN] = sigmoidf(a);
    }
}

// ---------------- K3b: pure streaming apply ----------------------------------
// one block per (b,c); 256 threads; att row held in registers (float4/thread),
// 16 independent t-rows streamed with full MLP.
__global__ void apply_kernel(const float* __restrict__ x, float* __restrict__ out) {
    const int bc  = blockIdx.x;          // b*CC + c
    const int tid = threadIdx.x;

    __shared__ float combs[TT];
    if (tid < TT) combs[tid] = g_comb[bc * TT + tid];

    const float4 a = ((const float4*)(g_att + (size_t)bc * HWN))[tid];
    __syncthreads();

    const float4* xp = (const float4*)(x + (size_t)bc * (TT * HWN));
    float4* op       = (float4*)(out + (size_t)bc * (TT * HWN));

#pragma unroll
    for (int t = 0; t < TT; t++) {
        const float s = combs[t];
        float4 v = xp[t * (HWN / 4) + tid];
        v.x = v.x * a.x * s;
        v.y = v.y * a.y * s;
        v.z = v.z * a.z * s;
        v.w = v.w * a.w * s;
        op[t * (HWN / 4) + tid] = v;
    }
}

// ---------------- launch -----------------------------------------------------
extern "C" void kernel_launch(void* const* d_in, const int* in_sizes, int n_in,
                              void* d_out, int out_size) {
    const float* x   = (const float*)d_in[0];
    const float* ws1 = (const float*)d_in[1];
    const float* bs1 = (const float*)d_in[2];
    const float* ws2 = (const float*)d_in[3];
    const float* bs2 = (const float*)d_in[4];
    const float* wt1 = (const float*)d_in[5];
    const float* bt1 = (const float*)d_in[6];
    const float* wt2 = (const float*)d_in[7];
    const float* bt2 = (const float*)d_in[8];
    const float* wc1 = (const float*)d_in[9];
    const float* bc1 = (const float*)d_in[10];
    const float* wc2 = (const float*)d_in[11];
    const float* bc2 = (const float*)d_in[12];
    float* out = (float*)d_out;

    pool_kernel<<<BB * CC, 256>>>(x);
    small_se_kernel<<<BB * TT, 256>>>(wt1, bt1, wt2, bt2, wc1, bc1, wc2, bc2);

    const int smem_bytes = K3A_SMEM_FLOATS * (int)sizeof(float);
    cudaFuncSetAttribute(spatial_se_kernel,
                         cudaFuncAttributeMaxDynamicSharedMemorySize, smem_bytes);
    spatial_se_kernel<<<BB * 32, 256, smem_bytes>>>(ws1, bs1, ws2, bs2);

    apply_kernel<<<BB * CC, 256>>>(x, out);
}